// round 2
// baseline (speedup 1.0000x reference)
#include <cuda_runtime.h>
#include <cuda_bf16.h>
#include <math.h>

#define NN 100000
#define NE 1600000
#define MY 64      // output feature dim
#define MIN 256    // input feature dim
#define NHID 64

// ---------------- static scratch (no allocation allowed) ----------------
__device__ float g_h0[NN * MY];        // MLP output / teleport term
__device__ float g_bufA[NN * MY];      // ping-pong buffer
__device__ int   g_deg[NN];            // in-degree (excl self loop)
__device__ float g_dinv[NN];           // 1/sqrt(deg+1)
__device__ int   g_rowptr[NN + 1];     // CSR row ptr (rows = dst)
__device__ int   g_cursor[NN];         // scatter cursors
__device__ int   g_col[NE];            // CSR col (= src)
__device__ float g_w[NE];              // CSR edge weight = dinv[src]*dinv[dst]

// ---------------- graph preprocessing ----------------
__global__ void k_zero() {
    int i = blockIdx.x * blockDim.x + threadIdx.x;
    if (i < NN) { g_deg[i] = 0; g_cursor[i] = 0; }
}

__global__ void k_degcount(const int* __restrict__ ei) {
    int e = blockIdx.x * blockDim.x + threadIdx.x;
    if (e < NE) {
        int d = ei[NE + e];
        atomicAdd(&g_deg[d], 1);
    }
}

__global__ void k_dinv() {
    int i = blockIdx.x * blockDim.x + threadIdx.x;
    if (i < NN) g_dinv[i] = rsqrtf((float)(g_deg[i] + 1));  // +1 self loop
}

// single-block exclusive scan of g_deg -> g_rowptr (Hillis-Steele per 1024 chunk)
__global__ void k_scan() {
    __shared__ int s[1024];
    __shared__ int carry_s;
    int tid = threadIdx.x;
    if (tid == 0) carry_s = 0;
    __syncthreads();
    for (int base = 0; base < NN; base += 1024) {
        int i = base + tid;
        int v = (i < NN) ? g_deg[i] : 0;
        s[tid] = v;
        __syncthreads();
        #pragma unroll
        for (int off = 1; off < 1024; off <<= 1) {
            int t2 = (tid >= off) ? s[tid - off] : 0;
            __syncthreads();
            s[tid] += t2;
            __syncthreads();
        }
        int carry = carry_s;
        if (i < NN) g_rowptr[i] = carry + s[tid] - v;   // exclusive
        __syncthreads();
        if (tid == 0) carry_s = carry + s[1023];
        __syncthreads();
    }
    if (tid == 0) g_rowptr[NN] = carry_s;
}

__global__ void k_scatter(const int* __restrict__ ei) {
    int e = blockIdx.x * blockDim.x + threadIdx.x;
    if (e < NE) {
        int srcv = ei[e];
        int dstv = ei[NE + e];
        int p = g_rowptr[dstv] + atomicAdd(&g_cursor[dstv], 1);
        g_col[p] = srcv;
        g_w[p] = g_dinv[srcv] * g_dinv[dstv];
    }
}

// ---------------- fused 2-layer MLP: g_h0 = relu(x@W1^T+b1)@W2^T+b2 ----------------
// 256 threads, 64-row tile, 4x4 register micro-tiles, K-chunks of 16 in smem.
__global__ void k_mlp(const float* __restrict__ x,
                      const float* __restrict__ W1,
                      const float* __restrict__ b1,
                      const float* __restrict__ W2,
                      const float* __restrict__ b2) {
    __shared__ float xs[16][68];    // xs[k][r]  (row stride 68 floats -> 16B aligned float4)
    __shared__ float ws[16][68];    // ws[k][j]
    __shared__ float hidT[64][68];  // hidT[c][r] (transposed hidden tile)

    int t = threadIdx.x;            // 0..255
    int tx = t & 15;                // micro-tile col group
    int ty = t >> 4;                // micro-tile row group
    int row0 = blockIdx.x * 64;

    float acc[4][4] = {};

    // ---- layer 1 ----
    for (int kk = 0; kk < MIN; kk += 16) {
        #pragma unroll
        for (int q = 0; q < 4; q++) {
            int i = t + q * 256;            // 0..1023
            int k = i & 15;
            int r = i >> 4;                 // 0..63
            int row = row0 + r;
            xs[k][r] = (row < NN) ? x[(size_t)row * MIN + kk + k] : 0.f;
            ws[k][r] = W1[(size_t)r * MIN + kk + k];  // r == j here (<64, valid)
        }
        __syncthreads();
        #pragma unroll
        for (int k = 0; k < 16; k++) {
            float4 av = *(const float4*)&xs[k][ty * 4];
            float4 bv = *(const float4*)&ws[k][tx * 4];
            float a0 = av.x, a1 = av.y, a2 = av.z, a3 = av.w;
            float b0v = bv.x, b1v = bv.y, b2v = bv.z, b3v = bv.w;
            acc[0][0] += a0 * b0v; acc[0][1] += a0 * b1v; acc[0][2] += a0 * b2v; acc[0][3] += a0 * b3v;
            acc[1][0] += a1 * b0v; acc[1][1] += a1 * b1v; acc[1][2] += a1 * b2v; acc[1][3] += a1 * b3v;
            acc[2][0] += a2 * b0v; acc[2][1] += a2 * b1v; acc[2][2] += a2 * b2v; acc[2][3] += a2 * b3v;
            acc[3][0] += a3 * b0v; acc[3][1] += a3 * b1v; acc[3][2] += a3 * b2v; acc[3][3] += a3 * b3v;
        }
        __syncthreads();
    }
    // bias + relu -> transposed hidden tile in smem
    #pragma unroll
    for (int j = 0; j < 4; j++) {
        float bj = b1[tx * 4 + j];
        #pragma unroll
        for (int i = 0; i < 4; i++) {
            float v = acc[i][j] + bj;
            hidT[tx * 4 + j][ty * 4 + i] = fmaxf(v, 0.f);
        }
    }
    __syncthreads();

    // ---- layer 2 ----
    float acc2[4][4] = {};
    for (int kk = 0; kk < NHID; kk += 16) {
        #pragma unroll
        for (int q = 0; q < 4; q++) {
            int i = t + q * 256;
            int k = i & 15;
            int j = i >> 4;                 // 0..63
            ws[k][j] = W2[(size_t)j * NHID + kk + k];
        }
        __syncthreads();
        #pragma unroll
        for (int k = 0; k < 16; k++) {
            float4 av = *(const float4*)&hidT[kk + k][ty * 4];
            float4 bv = *(const float4*)&ws[k][tx * 4];
            float a0 = av.x, a1 = av.y, a2 = av.z, a3 = av.w;
            float b0v = bv.x, b1v = bv.y, b2v = bv.z, b3v = bv.w;
            acc2[0][0] += a0 * b0v; acc2[0][1] += a0 * b1v; acc2[0][2] += a0 * b2v; acc2[0][3] += a0 * b3v;
            acc2[1][0] += a1 * b0v; acc2[1][1] += a1 * b1v; acc2[1][2] += a1 * b2v; acc2[1][3] += a1 * b3v;
            acc2[2][0] += a2 * b0v; acc2[2][1] += a2 * b1v; acc2[2][2] += a2 * b2v; acc2[2][3] += a2 * b3v;
            acc2[3][0] += a3 * b0v; acc2[3][1] += a3 * b1v; acc2[3][2] += a3 * b2v; acc2[3][3] += a3 * b3v;
        }
        __syncthreads();
    }
    // bias + store (float4 per row)
    #pragma unroll
    for (int i = 0; i < 4; i++) {
        int row = row0 + ty * 4 + i;
        if (row < NN) {
            float4 o;
            o.x = acc2[i][0] + b2[tx * 4 + 0];
            o.y = acc2[i][1] + b2[tx * 4 + 1];
            o.z = acc2[i][2] + b2[tx * 4 + 2];
            o.w = acc2[i][3] + b2[tx * 4 + 3];
            *(float4*)&g_h0[(size_t)row * MY + tx * 4] = o;
        }
    }
}

// ---------------- APPNP propagation step ----------------
// h_out[n] = 0.9 * (dinv[n]^2 * h_in[n] + sum_{e: dst=n} w_e * h_in[src_e]) + 0.1 * h0[n]
// block: (64 feat lanes) x (4 nodes)
__global__ void k_prop(const float* __restrict__ hin, float* __restrict__ hout) {
    int n = blockIdx.x * 4 + threadIdx.y;
    if (n >= NN) return;
    int f = threadIdx.x;                 // 0..63
    int start = g_rowptr[n];
    int end   = g_rowptr[n + 1];
    float dn = g_dinv[n];
    int idx = n * MY + f;
    float acc0 = dn * dn * __ldg(&hin[idx]);   // self loop
    float acc1 = 0.f, acc2 = 0.f, acc3 = 0.f;

    int p = start;
    for (; p + 4 <= end; p += 4) {
        int c0 = __ldg(&g_col[p + 0]);
        int c1 = __ldg(&g_col[p + 1]);
        int c2 = __ldg(&g_col[p + 2]);
        int c3 = __ldg(&g_col[p + 3]);
        float w0 = __ldg(&g_w[p + 0]);
        float w1 = __ldg(&g_w[p + 1]);
        float w2 = __ldg(&g_w[p + 2]);
        float w3 = __ldg(&g_w[p + 3]);
        float v0 = __ldg(&hin[c0 * MY + f]);
        float v1 = __ldg(&hin[c1 * MY + f]);
        float v2 = __ldg(&hin[c2 * MY + f]);
        float v3 = __ldg(&hin[c3 * MY + f]);
        acc0 = fmaf(w0, v0, acc0);
        acc1 = fmaf(w1, v1, acc1);
        acc2 = fmaf(w2, v2, acc2);
        acc3 = fmaf(w3, v3, acc3);
    }
    for (; p < end; ++p) {
        int c = __ldg(&g_col[p]);
        acc0 = fmaf(__ldg(&g_w[p]), __ldg(&hin[c * MY + f]), acc0);
    }
    float acc = (acc0 + acc1) + (acc2 + acc3);
    hout[idx] = fmaf(0.9f, acc, 0.1f * __ldg(&g_h0[idx]));
}

// ---------------- launch ----------------
extern "C" void kernel_launch(void* const* d_in, const int* in_sizes, int n_in,
                              void* d_out, int out_size) {
    // Bind inputs by element count (robust to metadata reordering).
    const float* x  = nullptr;
    const float* W1 = nullptr;
    const float* b1 = nullptr;
    const float* W2 = nullptr;
    const float* b2 = nullptr;
    const int*   ei = nullptr;   // edge_index is int32 (JAX x64 disabled)
    for (int i = 0; i < n_in; i++) {
        int s = in_sizes[i];
        if      (s == NN * MIN)   x  = (const float*)d_in[i];
        else if (s == NHID * MIN) W1 = (const float*)d_in[i];
        else if (s == MY * NHID)  W2 = (const float*)d_in[i];
        else if (s == 2 * NE)     ei = (const int*)d_in[i];
        else if (s == NHID) {
            if (!b1) b1 = (const float*)d_in[i];
            else     b2 = (const float*)d_in[i];
        }
    }

    float* d_h0   = nullptr;
    float* d_bufA = nullptr;
    cudaGetSymbolAddress((void**)&d_h0,   g_h0);
    cudaGetSymbolAddress((void**)&d_bufA, g_bufA);

    // graph preprocessing
    k_zero<<<(NN + 255) / 256, 256>>>();
    k_degcount<<<(NE + 255) / 256, 256>>>(ei);
    k_dinv<<<(NN + 255) / 256, 256>>>();
    k_scan<<<1, 1024>>>();
    k_scatter<<<(NE + 255) / 256, 256>>>(ei);

    // MLP
    k_mlp<<<(NN + 63) / 64, 256>>>(x, W1, b1, W2, b2);

    // K=10 propagation steps, ping-pong; even it -> bufA, odd it -> d_out
    dim3 pb(64, 4);
    int pg = (NN + 3) / 4;
    const float* hin = d_h0;
    for (int it = 0; it < 10; it++) {
        float* hout = (it & 1) ? (float*)d_out : d_bufA;
        k_prop<<<pg, pb>>>(hin, hout);
        hin = hout;
    }
    // final result landed in d_out (it=9 odd)
}

// round 3
// speedup vs baseline: 1.6927x; 1.6927x over previous
#include <cuda_runtime.h>
#include <cuda_bf16.h>
#include <math.h>

#define NN 100000
#define NE 1600000
#define MY 64      // output feature dim
#define MIN 256    // input feature dim
#define NHID 64
#define NBLK 98    // ceil(NN/1024)

// ---------------- static scratch (no allocation allowed) ----------------
__device__ float g_h0[NN * MY];        // MLP output / teleport term
__device__ float g_bufA[NN * MY];      // ping-pong buffer
__device__ int   g_deg[NN];            // in-degree (excl self loop)
__device__ float g_dinv[NN];           // 1/sqrt(deg+1)
__device__ int   g_rowptr[NN + 1];     // CSR row ptr (rows = dst)
__device__ int   g_cursor[NN];         // scatter cursors
__device__ int   g_col[NE];            // CSR col (= src)
__device__ float g_w[NE];              // CSR edge weight = dinv[src]*dinv[dst]
__device__ int   g_bsum[NBLK];         // per-block scan sums
__device__ int   g_boff[NBLK + 1];     // scanned block offsets

// ---------------- graph preprocessing ----------------
__global__ void k_zero() {
    int i = blockIdx.x * blockDim.x + threadIdx.x;
    if (i < NN) { g_deg[i] = 0; g_cursor[i] = 0; }
}

__global__ void k_degcount(const int* __restrict__ ei) {
    int e = blockIdx.x * blockDim.x + threadIdx.x;
    if (e < NE) {
        int d = ei[NE + e];
        atomicAdd(&g_deg[d], 1);
    }
}

// phase 1: per-block exclusive scan (warp shuffles) + block totals + dinv
__global__ void k_scan1() {
    __shared__ int wsum[32];
    int tid = threadIdx.x;
    int i = blockIdx.x * 1024 + tid;
    int v = (i < NN) ? g_deg[i] : 0;
    if (i < NN) g_dinv[i] = rsqrtf((float)(v + 1));   // fold dinv in
    int lane = tid & 31, w = tid >> 5;
    int x = v;
    #pragma unroll
    for (int o = 1; o < 32; o <<= 1) {
        int t = __shfl_up_sync(0xFFFFFFFFu, x, o);
        if (lane >= o) x += t;
    }
    if (lane == 31) wsum[w] = x;
    __syncthreads();
    if (w == 0) {
        int s = wsum[lane];
        #pragma unroll
        for (int o = 1; o < 32; o <<= 1) {
            int t = __shfl_up_sync(0xFFFFFFFFu, s, o);
            if (lane >= o) s += t;
        }
        wsum[lane] = s;
    }
    __syncthreads();
    int base = (w > 0) ? wsum[w - 1] : 0;
    if (i < NN) g_rowptr[i] = base + x - v;            // local exclusive
    if (tid == 1023) g_bsum[blockIdx.x] = base + x;    // block total
}

// phase 2: scan the 98 block sums (1 block, 128 threads)
__global__ void k_scan2() {
    __shared__ int s[128];
    int tid = threadIdx.x;
    int v = (tid < NBLK) ? g_bsum[tid] : 0;
    s[tid] = v;
    __syncthreads();
    #pragma unroll
    for (int o = 1; o < 128; o <<= 1) {
        int t = (tid >= o) ? s[tid - o] : 0;
        __syncthreads();
        s[tid] += t;
        __syncthreads();
    }
    if (tid < NBLK) g_boff[tid] = s[tid] - v;          // exclusive
    if (tid == NBLK - 1) g_boff[NBLK] = s[tid];        // grand total
}

// phase 3: add block offsets
__global__ void k_scan3() {
    int i = blockIdx.x * 1024 + threadIdx.x;
    if (i < NN) g_rowptr[i] += g_boff[blockIdx.x];
    if (i == 0) g_rowptr[NN] = g_boff[NBLK];
}

__global__ void k_scatter(const int* __restrict__ ei) {
    int e = blockIdx.x * blockDim.x + threadIdx.x;
    if (e < NE) {
        int srcv = ei[e];
        int dstv = ei[NE + e];
        int p = g_rowptr[dstv] + atomicAdd(&g_cursor[dstv], 1);
        g_col[p] = srcv;
        g_w[p] = g_dinv[srcv] * g_dinv[dstv];
    }
}

// ---------------- fused 2-layer MLP: g_h0 = relu(x@W1^T+b1)@W2^T+b2 ----------------
__global__ void k_mlp(const float* __restrict__ x,
                      const float* __restrict__ W1,
                      const float* __restrict__ b1,
                      const float* __restrict__ W2,
                      const float* __restrict__ b2) {
    __shared__ float xs[16][68];
    __shared__ float ws[16][68];
    __shared__ float hidT[64][68];

    int t = threadIdx.x;            // 0..255
    int tx = t & 15;
    int ty = t >> 4;
    int row0 = blockIdx.x * 64;

    float acc[4][4] = {};

    // ---- layer 1 ----
    for (int kk = 0; kk < MIN; kk += 16) {
        #pragma unroll
        for (int q = 0; q < 4; q++) {
            int i = t + q * 256;
            int k = i & 15;
            int r = i >> 4;
            int row = row0 + r;
            xs[k][r] = (row < NN) ? x[(size_t)row * MIN + kk + k] : 0.f;
            ws[k][r] = W1[(size_t)r * MIN + kk + k];
        }
        __syncthreads();
        #pragma unroll
        for (int k = 0; k < 16; k++) {
            float4 av = *(const float4*)&xs[k][ty * 4];
            float4 bv = *(const float4*)&ws[k][tx * 4];
            float a0 = av.x, a1 = av.y, a2 = av.z, a3 = av.w;
            float b0v = bv.x, b1v = bv.y, b2v = bv.z, b3v = bv.w;
            acc[0][0] += a0 * b0v; acc[0][1] += a0 * b1v; acc[0][2] += a0 * b2v; acc[0][3] += a0 * b3v;
            acc[1][0] += a1 * b0v; acc[1][1] += a1 * b1v; acc[1][2] += a1 * b2v; acc[1][3] += a1 * b3v;
            acc[2][0] += a2 * b0v; acc[2][1] += a2 * b1v; acc[2][2] += a2 * b2v; acc[2][3] += a2 * b3v;
            acc[3][0] += a3 * b0v; acc[3][1] += a3 * b1v; acc[3][2] += a3 * b2v; acc[3][3] += a3 * b3v;
        }
        __syncthreads();
    }
    #pragma unroll
    for (int j = 0; j < 4; j++) {
        float bj = b1[tx * 4 + j];
        #pragma unroll
        for (int i = 0; i < 4; i++) {
            float v = acc[i][j] + bj;
            hidT[tx * 4 + j][ty * 4 + i] = fmaxf(v, 0.f);
        }
    }
    __syncthreads();

    // ---- layer 2 ----
    float acc2[4][4] = {};
    for (int kk = 0; kk < NHID; kk += 16) {
        #pragma unroll
        for (int q = 0; q < 4; q++) {
            int i = t + q * 256;
            int k = i & 15;
            int j = i >> 4;
            ws[k][j] = W2[(size_t)j * NHID + kk + k];
        }
        __syncthreads();
        #pragma unroll
        for (int k = 0; k < 16; k++) {
            float4 av = *(const float4*)&hidT[kk + k][ty * 4];
            float4 bv = *(const float4*)&ws[k][tx * 4];
            float a0 = av.x, a1 = av.y, a2 = av.z, a3 = av.w;
            float b0v = bv.x, b1v = bv.y, b2v = bv.z, b3v = bv.w;
            acc2[0][0] += a0 * b0v; acc2[0][1] += a0 * b1v; acc2[0][2] += a0 * b2v; acc2[0][3] += a0 * b3v;
            acc2[1][0] += a1 * b0v; acc2[1][1] += a1 * b1v; acc2[1][2] += a1 * b2v; acc2[1][3] += a1 * b3v;
            acc2[2][0] += a2 * b0v; acc2[2][1] += a2 * b1v; acc2[2][2] += a2 * b2v; acc2[2][3] += a2 * b3v;
            acc2[3][0] += a3 * b0v; acc2[3][1] += a3 * b1v; acc2[3][2] += a3 * b2v; acc2[3][3] += a3 * b3v;
        }
        __syncthreads();
    }
    #pragma unroll
    for (int i = 0; i < 4; i++) {
        int row = row0 + ty * 4 + i;
        if (row < NN) {
            float4 o;
            o.x = acc2[i][0] + b2[tx * 4 + 0];
            o.y = acc2[i][1] + b2[tx * 4 + 1];
            o.z = acc2[i][2] + b2[tx * 4 + 2];
            o.w = acc2[i][3] + b2[tx * 4 + 3];
            *(float4*)&g_h0[(size_t)row * MY + tx * 4] = o;
        }
    }
}

// ---------------- APPNP propagation step (float2 lanes) ----------------
// block: (32 float2-lanes) x (8 nodes); warp = one node's full 64 features.
__global__ void k_prop(const float2* __restrict__ hin, float2* __restrict__ hout,
                       const float2* __restrict__ h0) {
    int n = blockIdx.x * 8 + threadIdx.y;
    if (n >= NN) return;
    int f = threadIdx.x;                 // 0..31 (float2 lanes)
    int start = g_rowptr[n];
    int end   = g_rowptr[n + 1];
    float dn = g_dinv[n];
    int idx = n * 32 + f;
    float2 hv = __ldg(&hin[idx]);
    float sl = dn * dn;
    float ax0 = sl * hv.x, ay0 = sl * hv.y;
    float ax1 = 0.f, ay1 = 0.f, ax2 = 0.f, ay2 = 0.f, ax3 = 0.f, ay3 = 0.f;

    int p = start;
    for (; p + 4 <= end; p += 4) {
        int c0 = __ldg(&g_col[p + 0]);
        int c1 = __ldg(&g_col[p + 1]);
        int c2 = __ldg(&g_col[p + 2]);
        int c3 = __ldg(&g_col[p + 3]);
        float w0 = __ldg(&g_w[p + 0]);
        float w1 = __ldg(&g_w[p + 1]);
        float w2 = __ldg(&g_w[p + 2]);
        float w3 = __ldg(&g_w[p + 3]);
        float2 v0 = __ldg(&hin[c0 * 32 + f]);
        float2 v1 = __ldg(&hin[c1 * 32 + f]);
        float2 v2 = __ldg(&hin[c2 * 32 + f]);
        float2 v3 = __ldg(&hin[c3 * 32 + f]);
        ax0 = fmaf(w0, v0.x, ax0); ay0 = fmaf(w0, v0.y, ay0);
        ax1 = fmaf(w1, v1.x, ax1); ay1 = fmaf(w1, v1.y, ay1);
        ax2 = fmaf(w2, v2.x, ax2); ay2 = fmaf(w2, v2.y, ay2);
        ax3 = fmaf(w3, v3.x, ax3); ay3 = fmaf(w3, v3.y, ay3);
    }
    for (; p < end; ++p) {
        int c = __ldg(&g_col[p]);
        float w = __ldg(&g_w[p]);
        float2 v = __ldg(&hin[c * 32 + f]);
        ax0 = fmaf(w, v.x, ax0); ay0 = fmaf(w, v.y, ay0);
    }
    float accx = (ax0 + ax1) + (ax2 + ax3);
    float accy = (ay0 + ay1) + (ay2 + ay3);
    float2 t0 = __ldg(&h0[idx]);
    float2 o;
    o.x = fmaf(0.9f, accx, 0.1f * t0.x);
    o.y = fmaf(0.9f, accy, 0.1f * t0.y);
    hout[idx] = o;
}

// ---------------- launch ----------------
extern "C" void kernel_launch(void* const* d_in, const int* in_sizes, int n_in,
                              void* d_out, int out_size) {
    // Bind inputs by element count (robust to metadata reordering).
    const float* x  = nullptr;
    const float* W1 = nullptr;
    const float* b1 = nullptr;
    const float* W2 = nullptr;
    const float* b2 = nullptr;
    const int*   ei = nullptr;   // edge_index is int32 (JAX x64 disabled)
    for (int i = 0; i < n_in; i++) {
        int s = in_sizes[i];
        if      (s == NN * MIN)   x  = (const float*)d_in[i];
        else if (s == NHID * MIN) W1 = (const float*)d_in[i];
        else if (s == MY * NHID)  W2 = (const float*)d_in[i];
        else if (s == 2 * NE)     ei = (const int*)d_in[i];
        else if (s == NHID) {
            if (!b1) b1 = (const float*)d_in[i];
            else     b2 = (const float*)d_in[i];
        }
    }

    float* d_h0   = nullptr;
    float* d_bufA = nullptr;
    cudaGetSymbolAddress((void**)&d_h0,   g_h0);
    cudaGetSymbolAddress((void**)&d_bufA, g_bufA);

    // graph preprocessing
    k_zero<<<(NN + 255) / 256, 256>>>();
    k_degcount<<<(NE + 255) / 256, 256>>>(ei);
    k_scan1<<<NBLK, 1024>>>();
    k_scan2<<<1, 128>>>();
    k_scan3<<<NBLK, 1024>>>();
    k_scatter<<<(NE + 255) / 256, 256>>>(ei);

    // MLP
    k_mlp<<<(NN + 63) / 64, 256>>>(x, W1, b1, W2, b2);

    // K=10 propagation steps, ping-pong; even it -> bufA, odd it -> d_out
    dim3 pb(32, 8);
    int pg = (NN + 7) / 8;
    const float* hin = d_h0;
    for (int it = 0; it < 10; it++) {
        float* hout = (it & 1) ? (float*)d_out : d_bufA;
        k_prop<<<pg, pb>>>((const float2*)hin, (float2*)hout, (const float2*)d_h0);
        hin = hout;
    }
    // final result landed in d_out (it=9 odd)
}

// round 4
// speedup vs baseline: 1.8963x; 1.1203x over previous
#include <cuda_runtime.h>
#include <cuda_fp16.h>
#include <math.h>

#define NN 100000
#define NE 1600000
#define MY 64      // output feature dim
#define MIN 256    // input feature dim
#define NHID 64
#define NBLK 98    // ceil(NN/1024)

// ---------------- static scratch (no allocation allowed) ----------------
__device__ float   g_h0[NN * MY];       // MLP output / teleport term (fp32)
__device__ __half2 g_hA[NN * 32];       // fp16 ping buffer (row = 128B = 1 L2 line)
__device__ __half2 g_hB[NN * 32];       // fp16 pong buffer
__device__ int     g_deg[NN];
__device__ float   g_dinv[NN];
__device__ int     g_rowptr[NN + 1];
__device__ int     g_cursor[NN];
__device__ int     g_col[NE];
__device__ float   g_w[NE];             // 0.9 * dinv[src] * dinv[dst]
__device__ int     g_bsum[NBLK];
__device__ int     g_boff[NBLK + 1];

// ---------------- graph preprocessing ----------------
__global__ void k_zero() {
    int i = blockIdx.x * blockDim.x + threadIdx.x;
    if (i < NN) { g_deg[i] = 0; g_cursor[i] = 0; }
}

__global__ void k_degcount(const int* __restrict__ ei) {
    int e = blockIdx.x * blockDim.x + threadIdx.x;
    if (e < NE) atomicAdd(&g_deg[ei[NE + e]], 1);
}

// phase 1: per-block exclusive scan + block totals + dinv
__global__ void k_scan1() {
    __shared__ int wsum[32];
    int tid = threadIdx.x;
    int i = blockIdx.x * 1024 + tid;
    int v = (i < NN) ? g_deg[i] : 0;
    if (i < NN) g_dinv[i] = rsqrtf((float)(v + 1));
    int lane = tid & 31, w = tid >> 5;
    int x = v;
    #pragma unroll
    for (int o = 1; o < 32; o <<= 1) {
        int t = __shfl_up_sync(0xFFFFFFFFu, x, o);
        if (lane >= o) x += t;
    }
    if (lane == 31) wsum[w] = x;
    __syncthreads();
    if (w == 0) {
        int s = wsum[lane];
        #pragma unroll
        for (int o = 1; o < 32; o <<= 1) {
            int t = __shfl_up_sync(0xFFFFFFFFu, s, o);
            if (lane >= o) s += t;
        }
        wsum[lane] = s;
    }
    __syncthreads();
    int base = (w > 0) ? wsum[w - 1] : 0;
    if (i < NN) g_rowptr[i] = base + x - v;
    if (tid == 1023) g_bsum[blockIdx.x] = base + x;
}

__global__ void k_scan2() {
    __shared__ int s[128];
    int tid = threadIdx.x;
    int v = (tid < NBLK) ? g_bsum[tid] : 0;
    s[tid] = v;
    __syncthreads();
    #pragma unroll
    for (int o = 1; o < 128; o <<= 1) {
        int t = (tid >= o) ? s[tid - o] : 0;
        __syncthreads();
        s[tid] += t;
        __syncthreads();
    }
    if (tid < NBLK) g_boff[tid] = s[tid] - v;
    if (tid == NBLK - 1) g_boff[NBLK] = s[tid];
}

__global__ void k_scan3() {
    int i = blockIdx.x * 1024 + threadIdx.x;
    if (i < NN) g_rowptr[i] += g_boff[blockIdx.x];
    if (i == 0) g_rowptr[NN] = g_boff[NBLK];
}

__global__ void k_scatter(const int* __restrict__ ei) {
    int e = blockIdx.x * blockDim.x + threadIdx.x;
    if (e < NE) {
        int srcv = ei[e];
        int dstv = ei[NE + e];
        int p = g_rowptr[dstv] + atomicAdd(&g_cursor[dstv], 1);
        g_col[p] = srcv;
        g_w[p] = 0.9f * g_dinv[srcv] * g_dinv[dstv];   // fold (1-alpha)
    }
}

// ---------------- fused 2-layer MLP: g_h0 = relu(x@W1^T+b1)@W2^T+b2 ----------------
// also emits the fp16 copy into g_hA (iteration-0 input)
__global__ void k_mlp(const float* __restrict__ x,
                      const float* __restrict__ W1,
                      const float* __restrict__ b1,
                      const float* __restrict__ W2,
                      const float* __restrict__ b2) {
    __shared__ float xs[16][68];
    __shared__ float ws[16][68];
    __shared__ float hidT[64][68];

    int t = threadIdx.x;            // 0..255
    int tx = t & 15;
    int ty = t >> 4;
    int row0 = blockIdx.x * 64;

    float acc[4][4] = {};

    // ---- layer 1 ----
    for (int kk = 0; kk < MIN; kk += 16) {
        #pragma unroll
        for (int q = 0; q < 4; q++) {
            int i = t + q * 256;
            int k = i & 15;
            int r = i >> 4;
            int row = row0 + r;
            xs[k][r] = (row < NN) ? x[(size_t)row * MIN + kk + k] : 0.f;
            ws[k][r] = W1[(size_t)r * MIN + kk + k];
        }
        __syncthreads();
        #pragma unroll
        for (int k = 0; k < 16; k++) {
            float4 av = *(const float4*)&xs[k][ty * 4];
            float4 bv = *(const float4*)&ws[k][tx * 4];
            float a0 = av.x, a1 = av.y, a2 = av.z, a3 = av.w;
            float b0v = bv.x, b1v = bv.y, b2v = bv.z, b3v = bv.w;
            acc[0][0] += a0 * b0v; acc[0][1] += a0 * b1v; acc[0][2] += a0 * b2v; acc[0][3] += a0 * b3v;
            acc[1][0] += a1 * b0v; acc[1][1] += a1 * b1v; acc[1][2] += a1 * b2v; acc[1][3] += a1 * b3v;
            acc[2][0] += a2 * b0v; acc[2][1] += a2 * b1v; acc[2][2] += a2 * b2v; acc[2][3] += a2 * b3v;
            acc[3][0] += a3 * b0v; acc[3][1] += a3 * b1v; acc[3][2] += a3 * b2v; acc[3][3] += a3 * b3v;
        }
        __syncthreads();
    }
    #pragma unroll
    for (int j = 0; j < 4; j++) {
        float bj = b1[tx * 4 + j];
        #pragma unroll
        for (int i = 0; i < 4; i++) {
            float v = acc[i][j] + bj;
            hidT[tx * 4 + j][ty * 4 + i] = fmaxf(v, 0.f);
        }
    }
    __syncthreads();

    // ---- layer 2 ----
    float acc2[4][4] = {};
    for (int kk = 0; kk < NHID; kk += 16) {
        #pragma unroll
        for (int q = 0; q < 4; q++) {
            int i = t + q * 256;
            int k = i & 15;
            int j = i >> 4;
            ws[k][j] = W2[(size_t)j * NHID + kk + k];
        }
        __syncthreads();
        #pragma unroll
        for (int k = 0; k < 16; k++) {
            float4 av = *(const float4*)&hidT[kk + k][ty * 4];
            float4 bv = *(const float4*)&ws[k][tx * 4];
            float a0 = av.x, a1 = av.y, a2 = av.z, a3 = av.w;
            float b0v = bv.x, b1v = bv.y, b2v = bv.z, b3v = bv.w;
            acc2[0][0] += a0 * b0v; acc2[0][1] += a0 * b1v; acc2[0][2] += a0 * b2v; acc2[0][3] += a0 * b3v;
            acc2[1][0] += a1 * b0v; acc2[1][1] += a1 * b1v; acc2[1][2] += a1 * b2v; acc2[1][3] += a1 * b3v;
            acc2[2][0] += a2 * b0v; acc2[2][1] += a2 * b1v; acc2[2][2] += a2 * b2v; acc2[2][3] += a2 * b3v;
            acc2[3][0] += a3 * b0v; acc2[3][1] += a3 * b1v; acc2[3][2] += a3 * b2v; acc2[3][3] += a3 * b3v;
        }
        __syncthreads();
    }
    #pragma unroll
    for (int i = 0; i < 4; i++) {
        int row = row0 + ty * 4 + i;
        if (row < NN) {
            float4 o;
            o.x = acc2[i][0] + b2[tx * 4 + 0];
            o.y = acc2[i][1] + b2[tx * 4 + 1];
            o.z = acc2[i][2] + b2[tx * 4 + 2];
            o.w = acc2[i][3] + b2[tx * 4 + 3];
            *(float4*)&g_h0[(size_t)row * MY + tx * 4] = o;
            // fp16 copy = iteration-0 input
            g_hA[row * 32 + tx * 2 + 0] = __floats2half2_rn(o.x, o.y);
            g_hA[row * 32 + tx * 2 + 1] = __floats2half2_rn(o.z, o.w);
        }
    }
}

// ---------------- APPNP propagation step (fp16 gathers, fp32 accumulate) ----------------
// block: (32 half2-lanes) x (8 nodes); warp = one node's 64 features = 128B = 1 line.
// h_out = selfw*h_self + sum w_e*h_src + 0.1*h0   (0.9 pre-folded into weights)
template <bool LAST>
__global__ void k_prop(const __half2* __restrict__ hin, __half2* __restrict__ hout,
                       const float2* __restrict__ h0, float2* __restrict__ outf) {
    int n = blockIdx.x * 8 + threadIdx.y;
    if (n >= NN) return;
    int f = threadIdx.x;                 // 0..31
    int start = g_rowptr[n];
    int end   = g_rowptr[n + 1];
    float dn = g_dinv[n];
    int idx = n * 32 + f;
    float2 hv = __half22float2(__ldg(&hin[idx]));
    float sl = 0.9f * dn * dn;
    float ax0 = sl * hv.x, ay0 = sl * hv.y;
    float ax1 = 0.f, ay1 = 0.f, ax2 = 0.f, ay2 = 0.f, ax3 = 0.f, ay3 = 0.f;

    int p = start;
    for (; p + 4 <= end; p += 4) {
        int c0 = __ldg(&g_col[p + 0]);
        int c1 = __ldg(&g_col[p + 1]);
        int c2 = __ldg(&g_col[p + 2]);
        int c3 = __ldg(&g_col[p + 3]);
        float w0 = __ldg(&g_w[p + 0]);
        float w1 = __ldg(&g_w[p + 1]);
        float w2 = __ldg(&g_w[p + 2]);
        float w3 = __ldg(&g_w[p + 3]);
        float2 v0 = __half22float2(__ldg(&hin[c0 * 32 + f]));
        float2 v1 = __half22float2(__ldg(&hin[c1 * 32 + f]));
        float2 v2 = __half22float2(__ldg(&hin[c2 * 32 + f]));
        float2 v3 = __half22float2(__ldg(&hin[c3 * 32 + f]));
        ax0 = fmaf(w0, v0.x, ax0); ay0 = fmaf(w0, v0.y, ay0);
        ax1 = fmaf(w1, v1.x, ax1); ay1 = fmaf(w1, v1.y, ay1);
        ax2 = fmaf(w2, v2.x, ax2); ay2 = fmaf(w2, v2.y, ay2);
        ax3 = fmaf(w3, v3.x, ax3); ay3 = fmaf(w3, v3.y, ay3);
    }
    for (; p < end; ++p) {
        int c = __ldg(&g_col[p]);
        float w = __ldg(&g_w[p]);
        float2 v = __half22float2(__ldg(&hin[c * 32 + f]));
        ax0 = fmaf(w, v.x, ax0); ay0 = fmaf(w, v.y, ay0);
    }
    float accx = (ax0 + ax1) + (ax2 + ax3);
    float accy = (ay0 + ay1) + (ay2 + ay3);
    float2 t0 = __ldg(&h0[idx]);
    float ox = fmaf(0.1f, t0.x, accx);
    float oy = fmaf(0.1f, t0.y, accy);
    if (LAST) {
        float2 o; o.x = ox; o.y = oy;
        outf[idx] = o;
    } else {
        hout[idx] = __floats2half2_rn(ox, oy);
    }
}

// ---------------- launch ----------------
extern "C" void kernel_launch(void* const* d_in, const int* in_sizes, int n_in,
                              void* d_out, int out_size) {
    // Bind inputs by element count (robust to metadata reordering).
    const float* x  = nullptr;
    const float* W1 = nullptr;
    const float* b1 = nullptr;
    const float* W2 = nullptr;
    const float* b2 = nullptr;
    const int*   ei = nullptr;   // edge_index is int32 (JAX x64 disabled)
    for (int i = 0; i < n_in; i++) {
        int s = in_sizes[i];
        if      (s == NN * MIN)   x  = (const float*)d_in[i];
        else if (s == NHID * MIN) W1 = (const float*)d_in[i];
        else if (s == MY * NHID)  W2 = (const float*)d_in[i];
        else if (s == 2 * NE)     ei = (const int*)d_in[i];
        else if (s == NHID) {
            if (!b1) b1 = (const float*)d_in[i];
            else     b2 = (const float*)d_in[i];
        }
    }

    float*   d_h0 = nullptr;
    __half2* d_hA = nullptr;
    __half2* d_hB = nullptr;
    cudaGetSymbolAddress((void**)&d_h0, g_h0);
    cudaGetSymbolAddress((void**)&d_hA, g_hA);
    cudaGetSymbolAddress((void**)&d_hB, g_hB);

    // graph preprocessing
    k_zero<<<(NN + 255) / 256, 256>>>();
    k_degcount<<<(NE + 255) / 256, 256>>>(ei);
    k_scan1<<<NBLK, 1024>>>();
    k_scan2<<<1, 128>>>();
    k_scan3<<<NBLK, 1024>>>();
    k_scatter<<<(NE + 255) / 256, 256>>>(ei);

    // MLP (also seeds g_hA with fp16 h0)
    k_mlp<<<(NN + 63) / 64, 256>>>(x, W1, b1, W2, b2);

    // K=10 propagation steps, fp16 ping-pong; last iter writes fp32 to d_out
    dim3 pb(32, 8);
    int pg = (NN + 7) / 8;
    const __half2* hin = d_hA;
    for (int it = 0; it < 9; it++) {
        __half2* hout = (it & 1) ? d_hA : d_hB;
        k_prop<false><<<pg, pb>>>(hin, hout, (const float2*)d_h0, nullptr);
        hin = hout;
    }
    k_prop<true><<<pg, pb>>>(hin, nullptr, (const float2*)d_h0, (float2*)d_out);
}